// round 1
// baseline (speedup 1.0000x reference)
#include <cuda_runtime.h>
#include <math.h>
#include <stdint.h>

#define BZ 32
#define SZ 512
#define DZ 1024
#define NHZ 16
#define DH 64
#define EZ 16
#define HZ 256
#define TZ (BZ*SZ)          // 16384 tokens
#define KTOP 8
#define LN_EPS 1e-5f
#define W_MI 5e-4f

// ---------------- scratch (static device arrays; no allocations) ----------------
__device__ float g_h[(size_t)TZ*DZ];            // LN1 out, later reused for LN3 out (h3)
__device__ float g_qkv[(size_t)TZ*3*DZ];        // qkv projection
__device__ float g_ctx[(size_t)TZ*DZ];          // attention context
__device__ float g_scores[(size_t)BZ*NHZ*SZ*SZ];// attention scores/probs
__device__ float g_u[(size_t)EZ*TZ*HZ];         // per-expert gated gelu activations
__device__ float g_gates[(size_t)TZ*EZ];        // dense top-k gates
__device__ float g_colsum[EZ];                  // column sums of probs (for aux loss)

// ---------------- LayerNorm: one block per row of 1024 ----------------
__global__ void ln_kernel(const float* __restrict__ in, const float* __restrict__ g,
                          const float* __restrict__ b, float* __restrict__ out)
{
    int t = blockIdx.x;
    int tid = threadIdx.x;            // 256 threads, 4 floats each
    const float4 v = reinterpret_cast<const float4*>(in + (size_t)t*DZ)[tid];
    float s  = v.x+v.y+v.z+v.w;
    float s2 = v.x*v.x+v.y*v.y+v.z*v.z+v.w*v.w;
    #pragma unroll
    for (int o=16;o>0;o>>=1){
        s  += __shfl_down_sync(0xffffffffu, s,  o);
        s2 += __shfl_down_sync(0xffffffffu, s2, o);
    }
    __shared__ float sm1[8], sm2[8];
    __shared__ float smv[2];
    int w = tid>>5, l = tid&31;
    if (l==0){ sm1[w]=s; sm2[w]=s2; }
    __syncthreads();
    if (tid==0){
        float a=0.f,c=0.f;
        #pragma unroll
        for (int i=0;i<8;i++){ a+=sm1[i]; c+=sm2[i]; }
        float m = a*(1.0f/DZ);
        float var = c*(1.0f/DZ) - m*m;
        smv[0]=m; smv[1]=rsqrtf(var+LN_EPS);
    }
    __syncthreads();
    float m=smv[0], r=smv[1];
    const float4 gg = reinterpret_cast<const float4*>(g)[tid];
    const float4 bb = reinterpret_cast<const float4*>(b)[tid];
    float4 o;
    o.x=(v.x-m)*r*gg.x+bb.x;
    o.y=(v.y-m)*r*gg.y+bb.y;
    o.z=(v.z-m)*r*gg.z+bb.z;
    o.w=(v.w-m)*r*gg.w+bb.w;
    reinterpret_cast<float4*>(out + (size_t)t*DZ)[tid] = o;
}

// ---------------- generic NT SGEMM: C = A[M,K] * B[N,K]^T + bias (+res) ----------------
// BM=BN=64, BK=16, 256 threads, 4x4 microtile
template<bool RES>
__global__ void gemm_nt_kernel(const float* __restrict__ A, const float* __restrict__ Bm,
                               const float* __restrict__ bias, const float* __restrict__ res,
                               float* __restrict__ C, int N, int Kd)
{
    __shared__ float As[16][68];
    __shared__ float Bs[16][68];
    int tid = threadIdx.x;
    int m0 = blockIdx.y*64, n0 = blockIdx.x*64;
    int ty = tid>>4, tx = tid&15;
    int lrow = tid>>2, lk = (tid&3)*4;
    const float* Aptr = A  + (size_t)(m0+lrow)*Kd + lk;
    const float* Bptr = Bm + (size_t)(n0+lrow)*Kd + lk;
    float acc[4][4] = {};
    for (int k0=0;k0<Kd;k0+=16){
        float4 av = *(const float4*)(Aptr + k0);
        float4 bv = *(const float4*)(Bptr + k0);
        As[lk+0][lrow]=av.x; As[lk+1][lrow]=av.y; As[lk+2][lrow]=av.z; As[lk+3][lrow]=av.w;
        Bs[lk+0][lrow]=bv.x; Bs[lk+1][lrow]=bv.y; Bs[lk+2][lrow]=bv.z; Bs[lk+3][lrow]=bv.w;
        __syncthreads();
        #pragma unroll
        for (int k=0;k<16;k++){
            float4 a  = *(const float4*)&As[k][ty*4];
            float4 b4 = *(const float4*)&Bs[k][tx*4];
            float ar[4]={a.x,a.y,a.z,a.w}, br[4]={b4.x,b4.y,b4.z,b4.w};
            #pragma unroll
            for (int i=0;i<4;i++)
                #pragma unroll
                for (int j=0;j<4;j++) acc[i][j] = fmaf(ar[i], br[j], acc[i][j]);
        }
        __syncthreads();
    }
    #pragma unroll
    for (int i=0;i<4;i++){
        int mr = m0+ty*4+i;
        float* crow = C + (size_t)mr*N + n0 + tx*4;
        #pragma unroll
        for (int j=0;j<4;j++){
            float vv = acc[i][j] + bias[n0+tx*4+j];
            if (RES) vv += res[(size_t)mr*N + n0 + tx*4 + j];
            crow[j]=vv;
        }
    }
}

// ---------------- QK^T per head: 64x64 tile, K=64 ----------------
__global__ void qk_kernel(const float* __restrict__ qkv, float* __restrict__ scores)
{
    __shared__ float Qs[64][68];
    __shared__ float Ks[64][68];
    int tid=threadIdx.x;
    int kt=blockIdx.x, qt=blockIdx.y, z=blockIdx.z;   // z = b*NH + h
    int b=z>>4, h=z&15;
    int t0=b*SZ;
    int lrow=tid>>2, lkq=tid&3;
    const float* Qbase = qkv + (size_t)(t0+qt*64+lrow)*(3*DZ) + h*DH;
    const float* Kbase = qkv + (size_t)(t0+kt*64+lrow)*(3*DZ) + DZ + h*DH;
    #pragma unroll
    for (int r=0;r<4;r++){
        int kk = lkq*4 + r*16;
        float4 qv = *(const float4*)(Qbase+kk);
        float4 kv = *(const float4*)(Kbase+kk);
        Qs[kk+0][lrow]=qv.x; Qs[kk+1][lrow]=qv.y; Qs[kk+2][lrow]=qv.z; Qs[kk+3][lrow]=qv.w;
        Ks[kk+0][lrow]=kv.x; Ks[kk+1][lrow]=kv.y; Ks[kk+2][lrow]=kv.z; Ks[kk+3][lrow]=kv.w;
    }
    __syncthreads();
    int ty=tid>>4, tx=tid&15;
    float acc[4][4]={};
    #pragma unroll 8
    for (int k=0;k<64;k++){
        float4 a  = *(const float4*)&Qs[k][ty*4];
        float4 b4 = *(const float4*)&Ks[k][tx*4];
        float ar[4]={a.x,a.y,a.z,a.w}, br[4]={b4.x,b4.y,b4.z,b4.w};
        #pragma unroll
        for (int i=0;i<4;i++)
            #pragma unroll
            for (int j=0;j<4;j++) acc[i][j] = fmaf(ar[i], br[j], acc[i][j]);
    }
    float* out = scores + (size_t)z*SZ*SZ;
    #pragma unroll
    for (int i=0;i<4;i++){
        int q = qt*64+ty*4+i;
        #pragma unroll
        for (int j=0;j<4;j++)
            out[(size_t)q*SZ + kt*64+tx*4+j] = acc[i][j]*0.125f;
    }
}

// ---------------- row softmax over 512, 128 threads per row ----------------
__global__ void softmax_kernel(float* __restrict__ scores)
{
    size_t row = blockIdx.x;
    int tid = threadIdx.x;            // 128
    float* p = scores + row*SZ;
    float4 v = reinterpret_cast<float4*>(p)[tid];
    float mx = fmaxf(fmaxf(v.x,v.y),fmaxf(v.z,v.w));
    __shared__ float sm[4];
    #pragma unroll
    for (int o=16;o>0;o>>=1) mx = fmaxf(mx, __shfl_down_sync(0xffffffffu,mx,o));
    int w=tid>>5, l=tid&31;
    if (l==0) sm[w]=mx;
    __syncthreads();
    mx = fmaxf(fmaxf(sm[0],sm[1]),fmaxf(sm[2],sm[3]));
    v.x=expf(v.x-mx); v.y=expf(v.y-mx); v.z=expf(v.z-mx); v.w=expf(v.w-mx);
    float s = v.x+v.y+v.z+v.w;
    #pragma unroll
    for (int o=16;o>0;o>>=1) s += __shfl_down_sync(0xffffffffu,s,o);
    __syncthreads();
    if (l==0) sm[w]=s;
    __syncthreads();
    s = sm[0]+sm[1]+sm[2]+sm[3];
    float r = 1.0f/s;
    v.x*=r; v.y*=r; v.z*=r; v.w*=r;
    reinterpret_cast<float4*>(p)[tid] = v;
}

// ---------------- attn @ V per head: out tile 64q x 64d, loop K=512 ----------------
__global__ void av_kernel(const float* __restrict__ scores, const float* __restrict__ qkv,
                          float* __restrict__ ctx)
{
    __shared__ float As[64][68];
    __shared__ float Vs[64][68];
    int tid=threadIdx.x;
    int qt=blockIdx.x, z=blockIdx.y;
    int b=z>>4, h=z&15;
    const float* S = scores + (size_t)z*SZ*SZ;
    int ty=tid>>4, tx=tid&15;
    int lrow=tid>>2, lkq=tid&3;
    int brow=tid>>4, bcol=(tid&15)*4;
    float acc[4][4]={};
    for (int kc=0;kc<8;kc++){
        #pragma unroll
        for (int r=0;r<4;r++){
            int kk=lkq*4+r*16;
            float4 a=*(const float4*)(S + (size_t)(qt*64+lrow)*SZ + kc*64+kk);
            As[kk+0][lrow]=a.x; As[kk+1][lrow]=a.y; As[kk+2][lrow]=a.z; As[kk+3][lrow]=a.w;
        }
        #pragma unroll
        for (int r=0;r<4;r++){
            int kr=brow + r*16;
            const float* vp = qkv + (size_t)(b*SZ + kc*64 + kr)*(3*DZ) + 2*DZ + h*DH + bcol;
            *(float4*)&Vs[kr][bcol] = *(const float4*)vp;
        }
        __syncthreads();
        #pragma unroll 8
        for (int k=0;k<64;k++){
            float4 a  = *(const float4*)&As[k][ty*4];
            float4 b4 = *(const float4*)&Vs[k][tx*4];
            float ar[4]={a.x,a.y,a.z,a.w}, br[4]={b4.x,b4.y,b4.z,b4.w};
            #pragma unroll
            for (int i=0;i<4;i++)
                #pragma unroll
                for (int j=0;j<4;j++) acc[i][j] = fmaf(ar[i], br[j], acc[i][j]);
        }
        __syncthreads();
    }
    #pragma unroll
    for (int i=0;i<4;i++){
        int q=qt*64+ty*4+i;
        float* o = ctx + (size_t)(b*SZ+q)*DZ + h*DH + tx*4;
        #pragma unroll
        for (int j=0;j<4;j++) o[j]=acc[i][j];
    }
}

// ---------------- gate: logits, softmax, top-8, probs out + colsum ----------------
__global__ void gate_kernel(const float* __restrict__ h3, const float* __restrict__ gate_w_all,
                            const int* __restrict__ task_id,
                            float* __restrict__ probs_out)
{
    int t = blockIdx.x;
    int tid = threadIdx.x;            // 256
    const float* gw = gate_w_all + (size_t)(*task_id)*DZ*EZ;
    float lacc[EZ];
    #pragma unroll
    for (int e=0;e<EZ;e++) lacc[e]=0.f;
    for (int d=tid; d<DZ; d+=256){
        float hv = h3[(size_t)t*DZ + d];
        const float* g = gw + d*EZ;
        #pragma unroll
        for (int e=0;e<EZ;e++) lacc[e] = fmaf(hv, g[e], lacc[e]);
    }
    #pragma unroll
    for (int o=16;o>0;o>>=1)
        #pragma unroll
        for (int e=0;e<EZ;e++) lacc[e] += __shfl_down_sync(0xffffffffu, lacc[e], o);
    __shared__ float sred[EZ][8];
    __shared__ float slog[EZ];
    int w=tid>>5, l=tid&31;
    if (l==0){
        #pragma unroll
        for (int e=0;e<EZ;e++) sred[e][w]=lacc[e];
    }
    __syncthreads();
    if (tid<EZ){
        float s=0;
        #pragma unroll
        for (int i=0;i<8;i++) s+=sred[tid][i];
        slog[tid]=s;
    }
    __syncthreads();
    if (tid==0){
        float mx=-1e30f;
        #pragma unroll
        for (int e=0;e<EZ;e++) mx=fmaxf(mx,slog[e]);
        float p[EZ]; float sum=0.f;
        #pragma unroll
        for (int e=0;e<EZ;e++){ p[e]=expf(slog[e]-mx); sum+=p[e]; }
        float inv=1.0f/sum;
        #pragma unroll
        for (int e=0;e<EZ;e++) p[e]*=inv;
        // top-8 (strict > : lowest index wins ties, matching lax.top_k)
        float tmp[EZ];
        #pragma unroll
        for (int e=0;e<EZ;e++) tmp[e]=p[e];
        float tv[KTOP]; int ti[KTOP]; float s8=0.f;
        for (int k=0;k<KTOP;k++){
            int bi=0; float bv=tmp[0];
            for (int e=1;e<EZ;e++){ if (tmp[e]>bv){ bv=tmp[e]; bi=e; } }
            tv[k]=bv; ti[k]=bi; tmp[bi]=-1e30f; s8+=bv;
        }
        float ginv = 1.0f/(s8 + 1e-6f);
        float gd[EZ];
        #pragma unroll
        for (int e=0;e<EZ;e++) gd[e]=0.f;
        for (int k=0;k<KTOP;k++) gd[ti[k]] = tv[k]*ginv;
        for (int e=0;e<EZ;e++){ g_gates[(size_t)t*EZ+e]=gd[e]; slog[e]=p[e]; }
    }
    __syncthreads();
    if (tid<EZ){
        probs_out[(size_t)t*EZ + tid] = slog[tid];
        atomicAdd(&g_colsum[tid], slog[tid]);
    }
}

__global__ void init_kernel()
{
    if (threadIdx.x < EZ) g_colsum[threadIdx.x]=0.f;
}

__global__ void finalize_kernel(float* __restrict__ aux)
{
    if (threadIdx.x==0){
        float a=0.f;
        #pragma unroll
        for (int e=0;e<EZ;e++){
            float m = g_colsum[e]*(1.0f/(float)TZ);
            a += m*logf(m+1e-6f);
        }
        *aux = W_MI*a;
    }
}

// ---------------- MoE GEMM1: U[e] = gate * gelu(h3 @ w1[e] + b1[e]) ----------------
__global__ void moe1_kernel(const float* __restrict__ h3, const float* __restrict__ w1,
                            const float* __restrict__ b1)
{
    __shared__ float As[16][68];
    __shared__ float Bs[16][68];
    int tid=threadIdx.x;
    int e = blockIdx.z;
    int m0=blockIdx.y*64, n0=blockIdx.x*64;
    int lrow=tid>>2, lk=(tid&3)*4;
    int bkr=tid>>4, bcol=(tid&15)*4;
    int ty=tid>>4, tx=tid&15;
    const float* Aptr = h3 + (size_t)(m0+lrow)*DZ + lk;
    const float* Bbase = w1 + (size_t)e*DZ*HZ;
    float acc[4][4]={};
    for (int k0=0;k0<DZ;k0+=16){
        float4 av = *(const float4*)(Aptr + k0);
        As[lk+0][lrow]=av.x; As[lk+1][lrow]=av.y; As[lk+2][lrow]=av.z; As[lk+3][lrow]=av.w;
        *(float4*)&Bs[bkr][bcol] = *(const float4*)(Bbase + (size_t)(k0+bkr)*HZ + n0 + bcol);
        __syncthreads();
        #pragma unroll
        for (int k=0;k<16;k++){
            float4 a  = *(const float4*)&As[k][ty*4];
            float4 b4 = *(const float4*)&Bs[k][tx*4];
            float ar[4]={a.x,a.y,a.z,a.w}, br[4]={b4.x,b4.y,b4.z,b4.w};
            #pragma unroll
            for (int i=0;i<4;i++)
                #pragma unroll
                for (int j=0;j<4;j++) acc[i][j] = fmaf(ar[i], br[j], acc[i][j]);
        }
        __syncthreads();
    }
    #pragma unroll
    for (int i=0;i<4;i++){
        int t=m0+ty*4+i;
        float gt = g_gates[(size_t)t*EZ+e];
        #pragma unroll
        for (int j=0;j<4;j++){
            int n=n0+tx*4+j;
            float vv = acc[i][j] + b1[e*HZ+n];
            float ge = 0.5f*vv*(1.0f+erff(vv*0.70710678118654752f));
            g_u[(size_t)e*TZ*HZ + (size_t)t*HZ + n] = ge*gt;
        }
    }
}

// ---------------- MoE GEMM2: out += sum_e U[e] @ w2[e] + gates @ b2 ----------------
__global__ void moe2_kernel(const float* __restrict__ w2, const float* __restrict__ b2,
                            float* __restrict__ out)
{
    __shared__ float As[16][68];
    __shared__ float Bs[16][68];
    __shared__ float gtile[64][16];
    __shared__ float btile[16][64];
    int tid=threadIdx.x;
    int m0=blockIdx.y*64, n0=blockIdx.x*64;
    int lrow=tid>>2, lk=(tid&3)*4;
    int bkr=tid>>4, bcol=(tid&15)*4;
    int ty=tid>>4, tx=tid&15;
    float acc[4][4]={};
    for (int e=0;e<EZ;e++){
        const float* Ae = g_u + (size_t)e*TZ*HZ;
        const float* Be = w2 + (size_t)e*HZ*DZ;
        for (int k0=0;k0<HZ;k0+=16){
            float4 av = *(const float4*)(Ae + (size_t)(m0+lrow)*HZ + k0+lk);
            As[lk+0][lrow]=av.x; As[lk+1][lrow]=av.y; As[lk+2][lrow]=av.z; As[lk+3][lrow]=av.w;
            *(float4*)&Bs[bkr][bcol] = *(const float4*)(Be + (size_t)(k0+bkr)*DZ + n0 + bcol);
            __syncthreads();
            #pragma unroll
            for (int k=0;k<16;k++){
                float4 a  = *(const float4*)&As[k][ty*4];
                float4 b4 = *(const float4*)&Bs[k][tx*4];
                float ar[4]={a.x,a.y,a.z,a.w}, br[4]={b4.x,b4.y,b4.z,b4.w};
                #pragma unroll
                for (int i=0;i<4;i++)
                    #pragma unroll
                    for (int j=0;j<4;j++) acc[i][j] = fmaf(ar[i], br[j], acc[i][j]);
            }
            __syncthreads();
        }
    }
    // stage gates[64x16] and b2 slice [16x64]
    {
        int idx = tid*4; int r = idx>>4, c = idx&15;
        *(float4*)&gtile[r][c] = *(const float4*)(g_gates + (size_t)(m0+r)*EZ + c);
        *(float4*)&btile[bkr][bcol] = *(const float4*)(b2 + (size_t)bkr*DZ + n0 + bcol);
    }
    __syncthreads();
    #pragma unroll
    for (int i=0;i<4;i++){
        int t=m0+ty*4+i;
        #pragma unroll
        for (int j=0;j<4;j++){
            float s=0.f;
            #pragma unroll
            for (int e=0;e<EZ;e++) s = fmaf(gtile[ty*4+i][e], btile[e][tx*4+j], s);
            size_t oi = (size_t)t*DZ + n0 + tx*4 + j;
            out[oi] += acc[i][j] + s;
        }
    }
}

// ---------------- launch ----------------
extern "C" void kernel_launch(void* const* d_in, const int* in_sizes, int n_in,
                              void* d_out, int out_size)
{
    const float* tgt        = (const float*)d_in[0];
    const float* ln1_g      = (const float*)d_in[2];
    const float* ln1_b      = (const float*)d_in[3];
    const float* ln3_g      = (const float*)d_in[4];
    const float* ln3_b      = (const float*)d_in[5];
    const float* in_proj_w  = (const float*)d_in[6];
    const float* in_proj_b  = (const float*)d_in[7];
    const float* out_proj_w = (const float*)d_in[8];
    const float* out_proj_b = (const float*)d_in[9];
    const float* gate_w     = (const float*)d_in[10];
    const float* w1         = (const float*)d_in[11];
    const float* b1         = (const float*)d_in[12];
    const float* w2         = (const float*)d_in[13];
    const float* b2         = (const float*)d_in[14];
    const int*   task_id    = (const int*)  d_in[15];

    float* out       = (float*)d_out;
    float* out_x     = out;                            // [T, D]
    float* out_aux   = out + (size_t)TZ*DZ;            // scalar
    float* out_probs = out + (size_t)TZ*DZ + 1;        // [T, E]

    float* hbuf; cudaGetSymbolAddress((void**)&hbuf, g_h);
    float* qkvbuf; cudaGetSymbolAddress((void**)&qkvbuf, g_qkv);
    float* ctxbuf; cudaGetSymbolAddress((void**)&ctxbuf, g_ctx);
    float* scoresbuf; cudaGetSymbolAddress((void**)&scoresbuf, g_scores);

    init_kernel<<<1,32>>>();

    // LN1
    ln_kernel<<<TZ,256>>>(tgt, ln1_g, ln1_b, hbuf);
    // QKV = h @ in_proj_w^T + b   (M=16384, N=3072, K=1024)
    gemm_nt_kernel<false><<<dim3(3*DZ/64, TZ/64), 256>>>(hbuf, in_proj_w, in_proj_b, nullptr, qkvbuf, 3*DZ, DZ);
    // scores = QK^T / 8
    qk_kernel<<<dim3(SZ/64, SZ/64, BZ*NHZ), 256>>>(qkvbuf, scoresbuf);
    // softmax rows
    softmax_kernel<<<(unsigned)((size_t)BZ*NHZ*SZ), 128>>>(scoresbuf);
    // ctx = attn @ V
    av_kernel<<<dim3(SZ/64, BZ*NHZ), 256>>>(scoresbuf, qkvbuf, ctxbuf);
    // x = tgt + ctx @ out_proj_w^T + b  -> written directly into d_out
    gemm_nt_kernel<true><<<dim3(DZ/64, TZ/64), 256>>>(ctxbuf, out_proj_w, out_proj_b, tgt, out_x, DZ, DZ);
    // LN3 -> h3 (reuse g_h)
    ln_kernel<<<TZ,256>>>(out_x, ln3_g, ln3_b, hbuf);
    // gating: probs + dense gates + colsum
    gate_kernel<<<TZ,256>>>(hbuf, gate_w, task_id, out_probs);
    finalize_kernel<<<1,32>>>(out_aux);
    // MoE expert GEMM1 (batched over experts)
    moe1_kernel<<<dim3(HZ/64, TZ/64, EZ), 256>>>(hbuf, w1, b1);
    // MoE GEMM2: accumulate all experts into out_x
    moe2_kernel<<<dim3(DZ/64, TZ/64), 256>>>(w2, b2, out_x);
}

// round 7
// speedup vs baseline: 2.5520x; 2.5520x over previous
#include <cuda_runtime.h>
#include <math.h>
#include <stdint.h>

#define BZ 32
#define SZ 512
#define DZ 1024
#define NHZ 16
#define DH 64
#define EZ 16
#define HZ 256
#define TZ (BZ*SZ)          // 16384 tokens
#define KTOP 8
#define LN_EPS 1e-5f
#define W_MI 5e-4f

// ---------------- scratch ----------------
__device__ float g_h[(size_t)TZ*DZ];
__device__ float g_qkv[(size_t)TZ*3*DZ];
__device__ float g_ctx[(size_t)TZ*DZ];
__device__ float g_scores[(size_t)BZ*NHZ*SZ*SZ];
__device__ float g_u[(size_t)EZ*TZ*HZ];
__device__ float g_gates[(size_t)TZ*EZ];
__device__ float g_colsum[EZ];
__device__ float g_w1t[(size_t)EZ*HZ*DZ];   // w1 -> [E][H][D] (K-major)
__device__ float g_w2t[(size_t)EZ*DZ*HZ];   // w2 -> [E][D][H] (K-major)

// =================== mma.sync tf32 helpers (baseline PTX, works on compute_103) ===================
__device__ __forceinline__ uint32_t f2tf(float x){
    uint32_t u; asm("cvt.rna.tf32.f32 %0, %1;" : "=r"(u) : "f"(x)); return u;
}
__device__ __forceinline__ void mma_tf32(float c[4], const uint32_t a[4], const uint32_t b[2]){
    asm volatile("mma.sync.aligned.m16n8k8.row.col.f32.tf32.tf32.f32 "
        "{%0,%1,%2,%3}, {%4,%5,%6,%7}, {%8,%9}, {%0,%1,%2,%3};"
        : "+f"(c[0]), "+f"(c[1]), "+f"(c[2]), "+f"(c[3])
        : "r"(a[0]), "r"(a[1]), "r"(a[2]), "r"(a[3]), "r"(b[0]), "r"(b[1]));
}

// SMEM geometry: A/B tiles [128][36] uint (pad 4), C staging [128][132] float
#define LDA_S 36
#define LDC_S 132
#define SMEM_DYN_BYTES (128*LDC_S*4)   // 67584 >= 2*128*36*4 = 36864

// =================== tensor-core GEMM: C[M,N] = A[M,K] * B[N,K]^T ===================
// MODE 0: C = acc + bias[n]                        (qkv)
// MODE 1: C = acc + bias[n] + res[m,n]             (out proj + residual)
// MODE 2: C = gelu(acc + b1[e,n]) * gates[m,e]     (moe1, blockIdx.z = expert, C->g_u)
template<int MODE>
__global__ void __launch_bounds__(256,2)
gemm_mma(const float* __restrict__ A, const float* __restrict__ Bm,
         const float* __restrict__ bias, const float* __restrict__ res,
         float* __restrict__ C, int Kd, int Ncols)
{
    extern __shared__ uint32_t smem_u[];
    uint32_t* As = smem_u;                // [128*36]
    uint32_t* Bs = smem_u + 128*LDA_S;    // [128*36]
    float*    Cs = (float*)smem_u;        // [128*132] (reuses A/B region in epilogue)
    __shared__ float sgate[128];

    int tid = threadIdx.x, lane = tid&31, wid = tid>>5;
    int m0 = blockIdx.y*128, n0 = blockIdx.x*128;
    int e = (MODE==2) ? blockIdx.z : 0;
    const float* Ab = A + (size_t)m0*Kd;
    const float* Bb = Bm + ((MODE==2) ? (size_t)e*HZ*Kd : (size_t)0) + (size_t)n0*Kd;
    int wm = (wid>>2)*64, wn = (wid&3)*32;
    int gr = lane>>2, gc = lane&3;

    float c[4][4][4];
    #pragma unroll
    for (int i=0;i<4;i++)
        #pragma unroll
        for (int j=0;j<4;j++)
            #pragma unroll
            for (int q=0;q<4;q++) c[i][j][q]=0.f;

    const int NC = Kd/32;
    for (int ch=0; ch<NC; ch++){
        const float* Ap = Ab + ch*32;
        const float* Bp = Bb + ch*32;
        #pragma unroll
        for (int j=0;j<4;j++){
            int idx = tid + j*256;
            int row = idx>>3, col = (idx&7)*4;
            float4 va = *(const float4*)(Ap + (size_t)row*Kd + col);
            float4 vb = *(const float4*)(Bp + (size_t)row*Kd + col);
            uint4 ua = make_uint4(f2tf(va.x),f2tf(va.y),f2tf(va.z),f2tf(va.w));
            uint4 ub = make_uint4(f2tf(vb.x),f2tf(vb.y),f2tf(vb.z),f2tf(vb.w));
            *(uint4*)&As[row*LDA_S+col] = ua;
            *(uint4*)&Bs[row*LDA_S+col] = ub;
        }
        __syncthreads();
        #pragma unroll
        for (int ks=0;ks<4;ks++){
            int k0 = ks*8;
            uint32_t a[4][4], b[4][2];
            #pragma unroll
            for (int mt=0;mt<4;mt++){
                int r = wm + mt*16 + gr;
                a[mt][0] = As[r*LDA_S + k0 + gc];
                a[mt][1] = As[(r+8)*LDA_S + k0 + gc];
                a[mt][2] = As[r*LDA_S + k0 + 4 + gc];
                a[mt][3] = As[(r+8)*LDA_S + k0 + 4 + gc];
            }
            #pragma unroll
            for (int nt=0;nt<4;nt++){
                int cc = wn + nt*8 + gr;
                b[nt][0] = Bs[cc*LDA_S + k0 + gc];
                b[nt][1] = Bs[cc*LDA_S + k0 + 4 + gc];
            }
            #pragma unroll
            for (int mt=0;mt<4;mt++)
                #pragma unroll
                for (int nt=0;nt<4;nt++)
                    mma_tf32(c[mt][nt], a[mt], b[nt]);
        }
        __syncthreads();
    }

    if (MODE==2 && tid<128) sgate[tid] = g_gates[(size_t)(m0+tid)*EZ + e];

    // stage accumulators into SMEM (row-major), then coalesced store
    #pragma unroll
    for (int mt=0;mt<4;mt++)
        #pragma unroll
        for (int nt=0;nt<4;nt++){
            int r = wm + mt*16 + gr, cc = wn + nt*8 + 2*gc;
            Cs[r*LDC_S + cc]     = c[mt][nt][0];
            Cs[r*LDC_S + cc + 1] = c[mt][nt][1];
            Cs[(r+8)*LDC_S + cc]     = c[mt][nt][2];
            Cs[(r+8)*LDC_S + cc + 1] = c[mt][nt][3];
        }
    __syncthreads();

    #pragma unroll
    for (int j=0;j<16;j++){
        int idx = tid + j*256;
        int row = idx>>5, c4 = (idx&31)*4;
        int rr = m0 + row, n = n0 + c4;
        float4 v = *(float4*)&Cs[row*LDC_S + c4];
        if (MODE==0){
            float4 bb = *(const float4*)(bias + n);
            v.x+=bb.x; v.y+=bb.y; v.z+=bb.z; v.w+=bb.w;
            *(float4*)(C + (size_t)rr*Ncols + n) = v;
        } else if (MODE==1){
            float4 bb = *(const float4*)(bias + n);
            float4 rs = *(const float4*)(res + (size_t)rr*Ncols + n);
            v.x+=bb.x+rs.x; v.y+=bb.y+rs.y; v.z+=bb.z+rs.z; v.w+=bb.w+rs.w;
            *(float4*)(C + (size_t)rr*Ncols + n) = v;
        } else {
            float4 bb = *(const float4*)(bias + e*HZ + n);
            float gt = sgate[row];
            float u0=v.x+bb.x, u1=v.y+bb.y, u2=v.z+bb.z, u3=v.w+bb.w;
            v.x = 0.5f*u0*(1.0f+erff(u0*0.70710678118654752f))*gt;
            v.y = 0.5f*u1*(1.0f+erff(u1*0.70710678118654752f))*gt;
            v.z = 0.5f*u2*(1.0f+erff(u2*0.70710678118654752f))*gt;
            v.w = 0.5f*u3*(1.0f+erff(u3*0.70710678118654752f))*gt;
            *(float4*)(C + ((size_t)e*TZ + rr)*HZ + n) = v;
        }
    }
}

// =================== MoE GEMM2: out[t,d] += sum_e U[e]@w2t[e]^T + gates@b2 ===================
__global__ void __launch_bounds__(256,2)
moe2_mma(const float* __restrict__ b2, float* __restrict__ C)
{
    extern __shared__ uint32_t smem_u[];
    uint32_t* As = smem_u;
    uint32_t* Bs = smem_u + 128*LDA_S;
    float*    Cs = (float*)smem_u;
    __shared__ float sgt[128*EZ];
    __shared__ float sb2[EZ*128];

    int tid = threadIdx.x, lane = tid&31, wid = tid>>5;
    int m0 = blockIdx.y*128, n0 = blockIdx.x*128;
    int wm = (wid>>2)*64, wn = (wid&3)*32;
    int gr = lane>>2, gc = lane&3;

    float c[4][4][4];
    #pragma unroll
    for (int i=0;i<4;i++)
        #pragma unroll
        for (int j=0;j<4;j++)
            #pragma unroll
            for (int q=0;q<4;q++) c[i][j][q]=0.f;

    const int NC = EZ * (HZ/32);   // 128 chunks
    for (int ch=0; ch<NC; ch++){
        int e = ch>>3, kk = (ch&7)*32;
        const float* Ap = g_u   + ((size_t)e*TZ + m0)*HZ + kk;
        const float* Bp = g_w2t + ((size_t)e*DZ + n0)*HZ + kk;
        #pragma unroll
        for (int j=0;j<4;j++){
            int idx = tid + j*256;
            int row = idx>>3, col = (idx&7)*4;
            float4 va = *(const float4*)(Ap + (size_t)row*HZ + col);
            float4 vb = *(const float4*)(Bp + (size_t)row*HZ + col);
            uint4 ua = make_uint4(f2tf(va.x),f2tf(va.y),f2tf(va.z),f2tf(va.w));
            uint4 ub = make_uint4(f2tf(vb.x),f2tf(vb.y),f2tf(vb.z),f2tf(vb.w));
            *(uint4*)&As[row*LDA_S+col] = ua;
            *(uint4*)&Bs[row*LDA_S+col] = ub;
        }
        __syncthreads();
        #pragma unroll
        for (int ks=0;ks<4;ks++){
            int k0 = ks*8;
            uint32_t a[4][4], b[4][2];
            #pragma unroll
            for (int mt=0;mt<4;mt++){
                int r = wm + mt*16 + gr;
                a[mt][0] = As[r*LDA_S + k0 + gc];
                a[mt][1] = As[(r+8)*LDA_S + k0 + gc];
                a[mt][2] = As[r*LDA_S + k0 + 4 + gc];
                a[mt][3] = As[(r+8)*LDA_S + k0 + 4 + gc];
            }
            #pragma unroll
            for (int nt=0;nt<4;nt++){
                int cc = wn + nt*8 + gr;
                b[nt][0] = Bs[cc*LDA_S + k0 + gc];
                b[nt][1] = Bs[cc*LDA_S + k0 + 4 + gc];
            }
            #pragma unroll
            for (int mt=0;mt<4;mt++)
                #pragma unroll
                for (int nt=0;nt<4;nt++)
                    mma_tf32(c[mt][nt], a[mt], b[nt]);
        }
        __syncthreads();
    }

    // preload gates tile [128][16] and b2 slice [16][128]
    if (tid < 128){
        const float* grw = g_gates + (size_t)(m0+tid)*EZ;
        #pragma unroll
        for (int q=0;q<4;q++) *(float4*)&sgt[tid*EZ + q*4] = *(const float4*)(grw + q*4);
    }
    #pragma unroll
    for (int j=0;j<2;j++){
        int idx = tid + j*256;       // 512 float4 slots over [16][128]
        int row = idx>>5, col = (idx&31)*4;
        *(float4*)&sb2[row*128 + col] = *(const float4*)(b2 + (size_t)row*DZ + n0 + col);
    }

    #pragma unroll
    for (int mt=0;mt<4;mt++)
        #pragma unroll
        for (int nt=0;nt<4;nt++){
            int r = wm + mt*16 + gr, cc = wn + nt*8 + 2*gc;
            Cs[r*LDC_S + cc]     = c[mt][nt][0];
            Cs[r*LDC_S + cc + 1] = c[mt][nt][1];
            Cs[(r+8)*LDC_S + cc]     = c[mt][nt][2];
            Cs[(r+8)*LDC_S + cc + 1] = c[mt][nt][3];
        }
    __syncthreads();

    #pragma unroll
    for (int j=0;j<16;j++){
        int idx = tid + j*256;
        int row = idx>>5, c4 = (idx&31)*4;
        int rr = m0 + row, n = n0 + c4;
        float4 v = *(float4*)&Cs[row*LDC_S + c4];
        float gb0=0.f, gb1=0.f, gb2v=0.f, gb3=0.f;
        #pragma unroll
        for (int q=0;q<EZ;q++){
            float gq = sgt[row*EZ+q];
            gb0 = fmaf(gq, sb2[q*128 + c4+0], gb0);
            gb1 = fmaf(gq, sb2[q*128 + c4+1], gb1);
            gb2v= fmaf(gq, sb2[q*128 + c4+2], gb2v);
            gb3 = fmaf(gq, sb2[q*128 + c4+3], gb3);
        }
        float* op = C + (size_t)rr*DZ + n;
        op[0] += v.x + gb0;
        op[1] += v.y + gb1;
        op[2] += v.z + gb2v;
        op[3] += v.w + gb3;
    }
}

// =================== weight transpose: src [z][R][Cc] -> dst [z][Cc][R] ===================
__global__ void transpose_k(const float* __restrict__ src, float* __restrict__ dst, int R, int Cc)
{
    __shared__ float t[32][33];
    int z = blockIdx.z;
    int r0 = blockIdx.y*32, c0 = blockIdx.x*32;
    const float* s = src + (size_t)z*R*Cc;
    float* d = dst + (size_t)z*R*Cc;
    int x = threadIdx.x, y = threadIdx.y;
    #pragma unroll
    for (int k=0;k<32;k+=8) t[y+k][x] = s[(size_t)(r0+y+k)*Cc + c0+x];
    __syncthreads();
    #pragma unroll
    for (int k=0;k<32;k+=8) d[(size_t)(c0+y+k)*R + r0+x] = t[x][y+k];
}

// =================== LayerNorm ===================
__global__ void ln_kernel(const float* __restrict__ in, const float* __restrict__ g,
                          const float* __restrict__ b, float* __restrict__ out)
{
    int t = blockIdx.x;
    int tid = threadIdx.x;
    const float4 v = reinterpret_cast<const float4*>(in + (size_t)t*DZ)[tid];
    float s  = v.x+v.y+v.z+v.w;
    float s2 = v.x*v.x+v.y*v.y+v.z*v.z+v.w*v.w;
    #pragma unroll
    for (int o=16;o>0;o>>=1){
        s  += __shfl_down_sync(0xffffffffu, s,  o);
        s2 += __shfl_down_sync(0xffffffffu, s2, o);
    }
    __shared__ float sm1[8], sm2[8];
    __shared__ float smv[2];
    int w = tid>>5, l = tid&31;
    if (l==0){ sm1[w]=s; sm2[w]=s2; }
    __syncthreads();
    if (tid==0){
        float a=0.f,c=0.f;
        #pragma unroll
        for (int i=0;i<8;i++){ a+=sm1[i]; c+=sm2[i]; }
        float m = a*(1.0f/DZ);
        float var = c*(1.0f/DZ) - m*m;
        smv[0]=m; smv[1]=rsqrtf(var+LN_EPS);
    }
    __syncthreads();
    float m=smv[0], r=smv[1];
    const float4 gg = reinterpret_cast<const float4*>(g)[tid];
    const float4 bb = reinterpret_cast<const float4*>(b)[tid];
    float4 o;
    o.x=(v.x-m)*r*gg.x+bb.x;
    o.y=(v.y-m)*r*gg.y+bb.y;
    o.z=(v.z-m)*r*gg.z+bb.z;
    o.w=(v.w-m)*r*gg.w+bb.w;
    reinterpret_cast<float4*>(out + (size_t)t*DZ)[tid] = o;
}

// =================== attention (SIMT) ===================
__global__ void qk_kernel(const float* __restrict__ qkv, float* __restrict__ scores)
{
    __shared__ float Qs[64][68];
    __shared__ float Ks[64][68];
    int tid=threadIdx.x;
    int kt=blockIdx.x, qt=blockIdx.y, z=blockIdx.z;
    int b=z>>4, h=z&15;
    int t0=b*SZ;
    int lrow=tid>>2, lkq=tid&3;
    const float* Qbase = qkv + (size_t)(t0+qt*64+lrow)*(3*DZ) + h*DH;
    const float* Kbase = qkv + (size_t)(t0+kt*64+lrow)*(3*DZ) + DZ + h*DH;
    #pragma unroll
    for (int r=0;r<4;r++){
        int kk = lkq*4 + r*16;
        float4 qv = *(const float4*)(Qbase+kk);
        float4 kv = *(const float4*)(Kbase+kk);
        Qs[kk+0][lrow]=qv.x; Qs[kk+1][lrow]=qv.y; Qs[kk+2][lrow]=qv.z; Qs[kk+3][lrow]=qv.w;
        Ks[kk+0][lrow]=kv.x; Ks[kk+1][lrow]=kv.y; Ks[kk+2][lrow]=kv.z; Ks[kk+3][lrow]=kv.w;
    }
    __syncthreads();
    int ty=tid>>4, tx=tid&15;
    float acc[4][4]={};
    #pragma unroll 8
    for (int k=0;k<64;k++){
        float4 a  = *(const float4*)&Qs[k][ty*4];
        float4 b4 = *(const float4*)&Ks[k][tx*4];
        float ar[4]={a.x,a.y,a.z,a.w}, br[4]={b4.x,b4.y,b4.z,b4.w};
        #pragma unroll
        for (int i=0;i<4;i++)
            #pragma unroll
            for (int j=0;j<4;j++) acc[i][j] = fmaf(ar[i], br[j], acc[i][j]);
    }
    float* out = scores + (size_t)z*SZ*SZ;
    #pragma unroll
    for (int i=0;i<4;i++){
        int q = qt*64+ty*4+i;
        #pragma unroll
        for (int j=0;j<4;j++)
            out[(size_t)q*SZ + kt*64+tx*4+j] = acc[i][j]*0.125f;
    }
}

__global__ void softmax_kernel(float* __restrict__ scores)
{
    size_t row = blockIdx.x;
    int tid = threadIdx.x;
    float* p = scores + row*SZ;
    float4 v = reinterpret_cast<float4*>(p)[tid];
    float mx = fmaxf(fmaxf(v.x,v.y),fmaxf(v.z,v.w));
    __shared__ float sm[4];
    #pragma unroll
    for (int o=16;o>0;o>>=1) mx = fmaxf(mx, __shfl_down_sync(0xffffffffu,mx,o));
    int w=tid>>5, l=tid&31;
    if (l==0) sm[w]=mx;
    __syncthreads();
    mx = fmaxf(fmaxf(sm[0],sm[1]),fmaxf(sm[2],sm[3]));
    v.x=expf(v.x-mx); v.y=expf(v.y-mx); v.z=expf(v.z-mx); v.w=expf(v.w-mx);
    float s = v.x+v.y+v.z+v.w;
    #pragma unroll
    for (int o=16;o>0;o>>=1) s += __shfl_down_sync(0xffffffffu,s,o);
    __syncthreads();
    if (l==0) sm[w]=s;
    __syncthreads();
    s = sm[0]+sm[1]+sm[2]+sm[3];
    float r = 1.0f/s;
    v.x*=r; v.y*=r; v.z*=r; v.w*=r;
    reinterpret_cast<float4*>(p)[tid] = v;
}

__global__ void av_kernel(const float* __restrict__ scores, const float* __restrict__ qkv,
                          float* __restrict__ ctx)
{
    __shared__ float As[64][68];
    __shared__ float Vs[64][68];
    int tid=threadIdx.x;
    int qt=blockIdx.x, z=blockIdx.y;
    int b=z>>4, h=z&15;
    const float* S = scores + (size_t)z*SZ*SZ;
    int ty=tid>>4, tx=tid&15;
    int lrow=tid>>2, lkq=tid&3;
    int brow=tid>>4, bcol=(tid&15)*4;
    float acc[4][4]={};
    for (int kc=0;kc<8;kc++){
        #pragma unroll
        for (int r=0;r<4;r++){
            int kk=lkq*4+r*16;
            float4 a=*(const float4*)(S + (size_t)(qt*64+lrow)*SZ + kc*64+kk);
            As[kk+0][lrow]=a.x; As[kk+1][lrow]=a.y; As[kk+2][lrow]=a.z; As[kk+3][lrow]=a.w;
        }
        #pragma unroll
        for (int r=0;r<4;r++){
            int kr=brow + r*16;
            const float* vp = qkv + (size_t)(b*SZ + kc*64 + kr)*(3*DZ) + 2*DZ + h*DH + bcol;
            *(float4*)&Vs[kr][bcol] = *(const float4*)vp;
        }
        __syncthreads();
        #pragma unroll 8
        for (int k=0;k<64;k++){
            float4 a  = *(const float4*)&As[k][ty*4];
            float4 b4 = *(const float4*)&Vs[k][tx*4];
            float ar[4]={a.x,a.y,a.z,a.w}, br[4]={b4.x,b4.y,b4.z,b4.w};
            #pragma unroll
            for (int i=0;i<4;i++)
                #pragma unroll
                for (int j=0;j<4;j++) acc[i][j] = fmaf(ar[i], br[j], acc[i][j]);
        }
        __syncthreads();
    }
    #pragma unroll
    for (int i=0;i<4;i++){
        int q=qt*64+ty*4+i;
        float* o = ctx + (size_t)(b*SZ+q)*DZ + h*DH + tx*4;
        #pragma unroll
        for (int j=0;j<4;j++) o[j]=acc[i][j];
    }
}

// =================== gating ===================
__global__ void gate_kernel(const float* __restrict__ h3, const float* __restrict__ gate_w_all,
                            const int* __restrict__ task_id,
                            float* __restrict__ probs_out)
{
    int t = blockIdx.x;
    int tid = threadIdx.x;
    const float* gw = gate_w_all + (size_t)(*task_id)*DZ*EZ;
    float lacc[EZ];
    #pragma unroll
    for (int e=0;e<EZ;e++) lacc[e]=0.f;
    for (int d=tid; d<DZ; d+=256){
        float hv = h3[(size_t)t*DZ + d];
        const float* g = gw + d*EZ;
        #pragma unroll
        for (int e=0;e<EZ;e++) lacc[e] = fmaf(hv, g[e], lacc[e]);
    }
    #pragma unroll
    for (int o=16;o>0;o>>=1)
        #pragma unroll
        for (int e=0;e<EZ;e++) lacc[e] += __shfl_down_sync(0xffffffffu, lacc[e], o);
    __shared__ float sred[EZ][8];
    __shared__ float slog[EZ];
    int w=tid>>5, l=tid&31;
    if (l==0){
        #pragma unroll
        for (int e=0;e<EZ;e++) sred[e][w]=lacc[e];
    }
    __syncthreads();
    if (tid<EZ){
        float s=0;
        #pragma unroll
        for (int i=0;i<8;i++) s+=sred[tid][i];
        slog[tid]=s;
    }
    __syncthreads();
    if (tid==0){
        float mx=-1e30f;
        #pragma unroll
        for (int e=0;e<EZ;e++) mx=fmaxf(mx,slog[e]);
        float p[EZ]; float sum=0.f;
        #pragma unroll
        for (int e=0;e<EZ;e++){ p[e]=expf(slog[e]-mx); sum+=p[e]; }
        float inv=1.0f/sum;
        #pragma unroll
        for (int e=0;e<EZ;e++) p[e]*=inv;
        float tmp[EZ];
        #pragma unroll
        for (int e=0;e<EZ;e++) tmp[e]=p[e];
        float tv[KTOP]; int ti[KTOP]; float s8=0.f;
        for (int k=0;k<KTOP;k++){
            int bi=0; float bv=tmp[0];
            for (int e=1;e<EZ;e++){ if (tmp[e]>bv){ bv=tmp[e]; bi=e; } }
            tv[k]=bv; ti[k]=bi; tmp[bi]=-1e30f; s8+=bv;
        }
        float ginv = 1.0f/(s8 + 1e-6f);
        float gd[EZ];
        #pragma unroll
        for (int e=0;e<EZ;e++) gd[e]=0.f;
        for (int k=0;k<KTOP;k++) gd[ti[k]] = tv[k]*ginv;
        for (int e=0;e<EZ;e++){ g_gates[(size_t)t*EZ+e]=gd[e]; slog[e]=p[e]; }
    }
    __syncthreads();
    if (tid<EZ){
        probs_out[(size_t)t*EZ + tid] = slog[tid];
        atomicAdd(&g_colsum[tid], slog[tid]);
    }
}

__global__ void init_kernel()
{
    if (threadIdx.x < EZ) g_colsum[threadIdx.x]=0.f;
}

__global__ void finalize_kernel(float* __restrict__ aux)
{
    if (threadIdx.x==0){
        float a=0.f;
        #pragma unroll
        for (int e=0;e<EZ;e++){
            float m = g_colsum[e]*(1.0f/(float)TZ);
            a += m*logf(m+1e-6f);
        }
        *aux = W_MI*a;
    }
}

// =================== launch ===================
extern "C" void kernel_launch(void* const* d_in, const int* in_sizes, int n_in,
                              void* d_out, int out_size)
{
    const float* tgt        = (const float*)d_in[0];
    const float* ln1_g      = (const float*)d_in[2];
    const float* ln1_b      = (const float*)d_in[3];
    const float* ln3_g      = (const float*)d_in[4];
    const float* ln3_b      = (const float*)d_in[5];
    const float* in_proj_w  = (const float*)d_in[6];
    const float* in_proj_b  = (const float*)d_in[7];
    const float* out_proj_w = (const float*)d_in[8];
    const float* out_proj_b = (const float*)d_in[9];
    const float* gate_w     = (const float*)d_in[10];
    const float* w1         = (const float*)d_in[11];
    const float* b1         = (const float*)d_in[12];
    const float* w2         = (const float*)d_in[13];
    const float* b2         = (const float*)d_in[14];
    const int*   task_id    = (const int*)  d_in[15];

    float* out       = (float*)d_out;
    float* out_x     = out;
    float* out_aux   = out + (size_t)TZ*DZ;
    float* out_probs = out + (size_t)TZ*DZ + 1;

    float* hbuf;      cudaGetSymbolAddress((void**)&hbuf, g_h);
    float* qkvbuf;    cudaGetSymbolAddress((void**)&qkvbuf, g_qkv);
    float* ctxbuf;    cudaGetSymbolAddress((void**)&ctxbuf, g_ctx);
    float* scoresbuf; cudaGetSymbolAddress((void**)&scoresbuf, g_scores);
    float* ubuf;      cudaGetSymbolAddress((void**)&ubuf, g_u);
    float* w1tbuf;    cudaGetSymbolAddress((void**)&w1tbuf, g_w1t);
    float* w2tbuf;    cudaGetSymbolAddress((void**)&w2tbuf, g_w2t);

    cudaFuncSetAttribute(gemm_mma<0>, cudaFuncAttributeMaxDynamicSharedMemorySize, SMEM_DYN_BYTES);
    cudaFuncSetAttribute(gemm_mma<1>, cudaFuncAttributeMaxDynamicSharedMemorySize, SMEM_DYN_BYTES);
    cudaFuncSetAttribute(gemm_mma<2>, cudaFuncAttributeMaxDynamicSharedMemorySize, SMEM_DYN_BYTES);
    cudaFuncSetAttribute(moe2_mma,    cudaFuncAttributeMaxDynamicSharedMemorySize, SMEM_DYN_BYTES);

    init_kernel<<<1,32>>>();

    // transpose MoE weights to K-major
    transpose_k<<<dim3(HZ/32, DZ/32, EZ), dim3(32,8)>>>(w1, w1tbuf, DZ, HZ);
    transpose_k<<<dim3(DZ/32, HZ/32, EZ), dim3(32,8)>>>(w2, w2tbuf, HZ, DZ);

    // LN1
    ln_kernel<<<TZ,256>>>(tgt, ln1_g, ln1_b, hbuf);
    // QKV = h @ in_proj_w^T + b
    gemm_mma<0><<<dim3(3*DZ/128, TZ/128), 256, SMEM_DYN_BYTES>>>(hbuf, in_proj_w, in_proj_b, nullptr, qkvbuf, DZ, 3*DZ);
    // attention
    qk_kernel<<<dim3(SZ/64, SZ/64, BZ*NHZ), 256>>>(qkvbuf, scoresbuf);
    softmax_kernel<<<(unsigned)((size_t)BZ*NHZ*SZ), 128>>>(scoresbuf);
    av_kernel<<<dim3(SZ/64, BZ*NHZ), 256>>>(scoresbuf, qkvbuf, ctxbuf);
    // x = tgt + ctx @ out_proj_w^T + b
    gemm_mma<1><<<dim3(DZ/128, TZ/128), 256, SMEM_DYN_BYTES>>>(ctxbuf, out_proj_w, out_proj_b, tgt, out_x, DZ, DZ);
    // LN3
    ln_kernel<<<TZ,256>>>(out_x, ln3_g, ln3_b, hbuf);
    // gating
    gate_kernel<<<TZ,256>>>(hbuf, gate_w, task_id, out_probs);
    finalize_kernel<<<1,32>>>(out_aux);
    // MoE GEMM1 (per-expert)
    gemm_mma<2><<<dim3(HZ/128, TZ/128, EZ), 256, SMEM_DYN_BYTES>>>(hbuf, w1tbuf, b1, nullptr, ubuf, DZ, HZ);
    // MoE GEMM2: accumulate into out_x
    moe2_mma<<<dim3(DZ/128, TZ/128), 256, SMEM_DYN_BYTES>>>(b2, out_x);
}